// round 1
// baseline (speedup 1.0000x reference)
#include <cuda_runtime.h>
#include <cstdint>

#define HN 16
#define DH 64
#define EM 1024
#define SQ 1024
#define BA 8
#define BH (BA*HN)
#define NTOK (BA*SQ)

// Scratch (device globals; allocation-free per harness rules)
__device__ float g_q[BH*SQ*DH];
__device__ float g_k[BH*SQ*DH];
__device__ float g_v[BH*SQ*DH];
__device__ float g_ctx[NTOK*EM];
__device__ float g_h[NTOK*EM];

__device__ __forceinline__ uint32_t f2tf(float f){
    uint32_t u; asm("cvt.rna.tf32.f32 %0, %1;" : "=r"(u) : "f"(f)); return u;
}
__device__ __forceinline__ void mma8(float c[4], const uint32_t a[4], uint32_t b0, uint32_t b1){
    asm volatile("mma.sync.aligned.m16n8k8.row.col.f32.tf32.tf32.f32 "
        "{%0,%1,%2,%3}, {%4,%5,%6,%7}, {%8,%9}, {%0,%1,%2,%3};\n"
        : "+f"(c[0]), "+f"(c[1]), "+f"(c[2]), "+f"(c[3])
        : "r"(a[0]), "r"(a[1]), "r"(a[2]), "r"(a[3]), "r"(b0), "r"(b1));
}

// ---------------------------------------------------------------------------
// Shared 128x128 GEMM tile core (A row-major [*,1024], W row-major [1024,*])
// 256 threads, warp grid 2x4 (warp tile 64x32), k-chunk 32.
// ---------------------------------------------------------------------------
__device__ __forceinline__ void gemm_tile(const float* __restrict__ A,
                                          const float* __restrict__ W,
                                          int arow_base, int nb,
                                          float c[4][4][4],
                                          float (*As)[36], float (*Bs)[132])
{
    int tid = threadIdx.x;
    int w = tid>>5, lane = tid&31, g = lane>>2, tig = lane&3;
    int rows0 = (w>>2)*64, cols0 = (w&3)*32;
    for (int k0=0; k0<EM; k0+=32){
        #pragma unroll
        for (int it=0; it<4; it++){
            int idx = tid + 256*it;
            int r = idx>>3, c4 = (idx&7)<<2;
            *(float4*)&As[r][c4] = *(const float4*)&A[(size_t)(arow_base+r)*EM + k0 + c4];
        }
        #pragma unroll
        for (int it=0; it<4; it++){
            int idx = tid + 256*it;
            int r = idx>>5, c4 = (idx&31)<<2;
            *(float4*)&Bs[r][c4] = *(const float4*)&W[(size_t)(k0+r)*EM + nb + c4];
        }
        __syncthreads();
        #pragma unroll
        for (int kk=0; kk<4; kk++){
            uint32_t a[4][4];
            #pragma unroll
            for (int mi=0; mi<4; mi++){
                int r = rows0 + 16*mi;
                a[mi][0]=f2tf(As[r+g  ][kk*8+tig  ]);
                a[mi][1]=f2tf(As[r+g+8][kk*8+tig  ]);
                a[mi][2]=f2tf(As[r+g  ][kk*8+tig+4]);
                a[mi][3]=f2tf(As[r+g+8][kk*8+tig+4]);
            }
            #pragma unroll
            for (int ni=0; ni<4; ni++){
                int n = cols0 + 8*ni;
                uint32_t b0 = f2tf(Bs[kk*8+tig  ][n+g]);
                uint32_t b1 = f2tf(Bs[kk*8+tig+4][n+g]);
                #pragma unroll
                for (int mi=0; mi<4; mi++) mma8(c[mi][ni], a[mi], b0, b1);
            }
        }
        __syncthreads();
    }
}

// ---------------------------------------------------------------------------
// K1: fused QKV projection.  grid (24, 64): x = colTile (8 per matrix * 3), y = rowTile
// ---------------------------------------------------------------------------
__global__ __launch_bounds__(256,1) void qkv_kernel(const float* __restrict__ hidden,
    const float* __restrict__ Wq, const float* __restrict__ bq,
    const float* __restrict__ Wk, const float* __restrict__ bk,
    const float* __restrict__ Wv, const float* __restrict__ bv)
{
    __shared__ float As[128][36];
    __shared__ float Bs[32][132];
    int ct = blockIdx.x, rt = blockIdx.y;
    int mat = ct>>3, nb = (ct&7)*128;
    const float* W    = (mat==0) ? Wq : (mat==1 ? Wk : Wv);
    const float* bias = (mat==0) ? bq : (mat==1 ? bk : bv);
    float* outp       = (mat==0) ? g_q : (mat==1 ? g_k : g_v);

    float c[4][4][4];
    #pragma unroll
    for (int i=0;i<4;i++)
        #pragma unroll
        for (int j=0;j<4;j++)
            #pragma unroll
            for (int e=0;e<4;e++) c[i][j][e]=0.f;

    gemm_tile(hidden, W, rt*128, nb, c, As, Bs);

    int tid=threadIdx.x, w=tid>>5, lane=tid&31, g=lane>>2, tig=lane&3;
    int rows0=(w>>2)*64, cols0=(w&3)*32;
    #pragma unroll
    for (int mi=0; mi<4; mi++){
        #pragma unroll
        for (int ni=0; ni<4; ni++){
            #pragma unroll
            for (int eo=0; eo<4; eo++){
                int row = rows0 + 16*mi + g + ((eo>=2)?8:0);
                int col = cols0 + 8*ni + 2*tig + (eo&1);
                int t = rt*128 + row;       // token index
                int e = nb + col;           // out feature within matrix
                float val = c[mi][ni][eo] + bias[e];
                int bb = t>>10, s = t&1023, h = e>>6, d = e&63;
                outp[((size_t)((bb<<4)+h)*SQ + s)*DH + d] = val;
            }
        }
    }
}

// ---------------------------------------------------------------------------
// K2: flash attention with relative_key_query bias.  grid (128, 8)
// ---------------------------------------------------------------------------
#define LDQ 68
#define LDSS 132
#define ATTN_SMEM ((128*LDQ + 128*LDQ + 256*LDQ + 128*LDSS + 3*128)*4)

__global__ __launch_bounds__(256,1) void attn_kernel(const float* __restrict__ dist_emb)
{
    extern __shared__ float sm[];
    float* Qs   = sm;                    // [128][LDQ]
    float* KVs  = Qs  + 128*LDQ;         // [128][LDQ]  K then V (re-used)
    float* Db   = KVs + 128*LDQ;         // [256][LDQ]  dist band
    float* Ss   = Db  + 256*LDQ;         // [128][LDSS] scores / probs
    float* m_sm = Ss  + 128*LDSS;        // [128]
    float* l_sm = m_sm + 128;            // [128]
    float* a_sm = l_sm + 128;            // [128]

    int bh = blockIdx.x;
    int l0 = blockIdx.y*128;
    int tid = threadIdx.x;
    int w = tid>>5, lane = tid&31, g = lane>>2, tig = lane&3;

    const float* qptr = g_q + ((size_t)bh*SQ + l0)*DH;
    #pragma unroll
    for (int it=0; it<8; it++){
        int idx = tid + 256*it;
        int r = idx>>4, c4 = (idx&15)<<2;
        *(float4*)&Qs[r*LDQ + c4] = *(const float4*)&qptr[r*DH + c4];
    }
    if (tid < 128){ m_sm[tid] = -1e30f; l_sm[tid] = 0.f; }
    float o[8][4];
    #pragma unroll
    for (int i=0;i<8;i++){ o[i][0]=0.f; o[i][1]=0.f; o[i][2]=0.f; o[i][3]=0.f; }
    __syncthreads();

    for (int rt=0; rt<8; rt++){
        int r0 = rt*128;
        const float* kptr = g_k + ((size_t)bh*SQ + r0)*DH;
        #pragma unroll
        for (int it=0; it<8; it++){
            int idx = tid + 256*it;
            int r = idx>>4, c4 = (idx&15)<<2;
            *(float4*)&KVs[r*LDQ + c4] = *(const float4*)&kptr[r*DH + c4];
        }
        // dist band: rows [base, base+254], t = i - jj + 127
        int base = l0 - r0 + 896;
        const float* dptr = dist_emb + (size_t)base*DH;
        for (int idx = tid; idx < 255*16; idx += 256){
            int r = idx>>4, c4 = (idx&15)<<2;
            *(float4*)&Db[r*LDQ + c4] = *(const float4*)&dptr[r*DH + c4];
        }
        if (tid < 16){ *(float4*)&Db[255*LDQ + tid*4] = make_float4(0.f,0.f,0.f,0.f); }
        __syncthreads();

        // ---- S = Q @ K^T (warp grid 4x2, warp tile 32x64) ----
        {
            int rows0 = (w>>1)*32, cols0 = (w&1)*64;
            float c[2][8][4];
            #pragma unroll
            for (int i=0;i<2;i++)
                #pragma unroll
                for (int j=0;j<8;j++){ c[i][j][0]=0.f; c[i][j][1]=0.f; c[i][j][2]=0.f; c[i][j][3]=0.f; }
            #pragma unroll
            for (int kk=0; kk<8; kk++){
                uint32_t a[2][4];
                #pragma unroll
                for (int mi=0; mi<2; mi++){
                    int r = rows0 + 16*mi;
                    a[mi][0]=f2tf(Qs[(r+g  )*LDQ + kk*8+tig  ]);
                    a[mi][1]=f2tf(Qs[(r+g+8)*LDQ + kk*8+tig  ]);
                    a[mi][2]=f2tf(Qs[(r+g  )*LDQ + kk*8+tig+4]);
                    a[mi][3]=f2tf(Qs[(r+g+8)*LDQ + kk*8+tig+4]);
                }
                #pragma unroll
                for (int ni=0; ni<8; ni++){
                    int n = cols0 + 8*ni;
                    uint32_t b0=f2tf(KVs[(n+g)*LDQ + kk*8+tig  ]);
                    uint32_t b1=f2tf(KVs[(n+g)*LDQ + kk*8+tig+4]);
                    mma8(c[0][ni], a[0], b0, b1);
                    mma8(c[1][ni], a[1], b0, b1);
                }
            }
            #pragma unroll
            for (int mi=0; mi<2; mi++)
                #pragma unroll
                for (int ni=0; ni<8; ni++){
                    int row = rows0+16*mi+g, col = cols0+8*ni+2*tig;
                    Ss[row*LDSS+col]       = c[mi][ni][0];
                    Ss[row*LDSS+col+1]     = c[mi][ni][1];
                    Ss[(row+8)*LDSS+col]   = c[mi][ni][2];
                    Ss[(row+8)*LDSS+col+1] = c[mi][ni][3];
                }
        }
        __syncthreads();

        // ---- rel_q: QD = Q @ Dband^T, scatter S[i][i+127-t] += QD[i][t] ----
        {
            int rows0 = (w>>1)*32;
            #pragma unroll
            for (int ch=0; ch<4; ch++){
                int tb = ch*64 + (w&1)*32;
                float c[2][4][4];
                #pragma unroll
                for (int i=0;i<2;i++)
                    #pragma unroll
                    for (int j=0;j<4;j++){ c[i][j][0]=0.f; c[i][j][1]=0.f; c[i][j][2]=0.f; c[i][j][3]=0.f; }
                #pragma unroll
                for (int kk=0; kk<8; kk++){
                    uint32_t a[2][4];
                    #pragma unroll
                    for (int mi=0; mi<2; mi++){
                        int r = rows0 + 16*mi;
                        a[mi][0]=f2tf(Qs[(r+g  )*LDQ + kk*8+tig  ]);
                        a[mi][1]=f2tf(Qs[(r+g+8)*LDQ + kk*8+tig  ]);
                        a[mi][2]=f2tf(Qs[(r+g  )*LDQ + kk*8+tig+4]);
                        a[mi][3]=f2tf(Qs[(r+g+8)*LDQ + kk*8+tig+4]);
                    }
                    #pragma unroll
                    for (int ni=0; ni<4; ni++){
                        int n = tb + 8*ni;
                        uint32_t b0=f2tf(Db[(n+g)*LDQ + kk*8+tig  ]);
                        uint32_t b1=f2tf(Db[(n+g)*LDQ + kk*8+tig+4]);
                        mma8(c[0][ni], a[0], b0, b1);
                        mma8(c[1][ni], a[1], b0, b1);
                    }
                }
                #pragma unroll
                for (int mi=0; mi<2; mi++)
                    #pragma unroll
                    for (int ni=0; ni<4; ni++){
                        int i0 = rows0+16*mi+g;
                        int t0 = tb+8*ni+2*tig;
                        #pragma unroll
                        for (int eo=0; eo<4; eo++){
                            int i = i0 + ((eo>=2)?8:0);
                            int t = t0 + (eo&1);
                            int jj = i + 127 - t;
                            if ((unsigned)jj < 128u) Ss[i*LDSS + jj] += c[mi][ni][eo];
                        }
                    }
            }
        }
        __syncthreads();

        // ---- rel_k: KD = K @ Dband^T, scatter S[t+r-127][r] += KD[r][t] ----
        {
            int rows0 = (w>>1)*32;
            #pragma unroll
            for (int ch=0; ch<4; ch++){
                int tb = ch*64 + (w&1)*32;
                float c[2][4][4];
                #pragma unroll
                for (int i=0;i<2;i++)
                    #pragma unroll
                    for (int j=0;j<4;j++){ c[i][j][0]=0.f; c[i][j][1]=0.f; c[i][j][2]=0.f; c[i][j][3]=0.f; }
                #pragma unroll
                for (int kk=0; kk<8; kk++){
                    uint32_t a[2][4];
                    #pragma unroll
                    for (int mi=0; mi<2; mi++){
                        int r = rows0 + 16*mi;
                        a[mi][0]=f2tf(KVs[(r+g  )*LDQ + kk*8+tig  ]);
                        a[mi][1]=f2tf(KVs[(r+g+8)*LDQ + kk*8+tig  ]);
                        a[mi][2]=f2tf(KVs[(r+g  )*LDQ + kk*8+tig+4]);
                        a[mi][3]=f2tf(KVs[(r+g+8)*LDQ + kk*8+tig+4]);
                    }
                    #pragma unroll
                    for (int ni=0; ni<4; ni++){
                        int n = tb + 8*ni;
                        uint32_t b0=f2tf(Db[(n+g)*LDQ + kk*8+tig  ]);
                        uint32_t b1=f2tf(Db[(n+g)*LDQ + kk*8+tig+4]);
                        mma8(c[0][ni], a[0], b0, b1);
                        mma8(c[1][ni], a[1], b0, b1);
                    }
                }
                #pragma unroll
                for (int mi=0; mi<2; mi++)
                    #pragma unroll
                    for (int ni=0; ni<4; ni++){
                        int r0c = rows0+16*mi+g;
                        int t0 = tb+8*ni+2*tig;
                        #pragma unroll
                        for (int eo=0; eo<4; eo++){
                            int r = r0c + ((eo>=2)?8:0);
                            int t = t0 + (eo&1);
                            int i = t + r - 127;
                            if ((unsigned)i < 128u) Ss[i*LDSS + r] += c[mi][ni][eo];
                        }
                    }
            }
        }
        __syncthreads();

        // ---- load V into KVs (K no longer needed) ----
        const float* vptr = g_v + ((size_t)bh*SQ + r0)*DH;
        #pragma unroll
        for (int it=0; it<8; it++){
            int idx = tid + 256*it;
            int r = idx>>4, c4 = (idx&15)<<2;
            *(float4*)&KVs[r*LDQ + c4] = *(const float4*)&vptr[r*DH + c4];
        }

        // ---- online softmax (warp w owns rows 16w..16w+15) ----
        #pragma unroll 1
        for (int rr=0; rr<16; rr++){
            int row = w*16 + rr;
            float v0 = Ss[row*LDSS + lane     ] * 0.125f;
            float v1 = Ss[row*LDSS + lane + 32] * 0.125f;
            float v2 = Ss[row*LDSS + lane + 64] * 0.125f;
            float v3 = Ss[row*LDSS + lane + 96] * 0.125f;
            float mx = fmaxf(fmaxf(v0,v1), fmaxf(v2,v3));
            #pragma unroll
            for (int off=16; off; off>>=1) mx = fmaxf(mx, __shfl_xor_sync(0xffffffffu, mx, off));
            float mo = m_sm[row];
            float mn = fmaxf(mo, mx);
            float p0 = __expf(v0-mn), p1 = __expf(v1-mn), p2 = __expf(v2-mn), p3 = __expf(v3-mn);
            float sum = p0+p1+p2+p3;
            #pragma unroll
            for (int off=16; off; off>>=1) sum += __shfl_xor_sync(0xffffffffu, sum, off);
            Ss[row*LDSS + lane     ] = p0;
            Ss[row*LDSS + lane + 32] = p1;
            Ss[row*LDSS + lane + 64] = p2;
            Ss[row*LDSS + lane + 96] = p3;
            if (lane==0){
                float al = __expf(mo - mn);
                a_sm[row] = al;
                l_sm[row] = l_sm[row]*al + sum;
                m_sm[row] = mn;
            }
        }
        __syncthreads();

        // ---- rescale O and accumulate O += P @ V (warp tile 16x64) ----
        {
            float al0 = a_sm[w*16+g], al1 = a_sm[w*16+g+8];
            #pragma unroll
            for (int ni=0; ni<8; ni++){ o[ni][0]*=al0; o[ni][1]*=al0; o[ni][2]*=al1; o[ni][3]*=al1; }
            #pragma unroll
            for (int kk=0; kk<16; kk++){
                uint32_t a[4];
                a[0]=f2tf(Ss[(w*16+g  )*LDSS + kk*8+tig  ]);
                a[1]=f2tf(Ss[(w*16+g+8)*LDSS + kk*8+tig  ]);
                a[2]=f2tf(Ss[(w*16+g  )*LDSS + kk*8+tig+4]);
                a[3]=f2tf(Ss[(w*16+g+8)*LDSS + kk*8+tig+4]);
                #pragma unroll
                for (int ni=0; ni<8; ni++){
                    uint32_t b0=f2tf(KVs[(kk*8+tig  )*LDQ + ni*8+g]);
                    uint32_t b1=f2tf(KVs[(kk*8+tig+4)*LDQ + ni*8+g]);
                    mma8(o[ni], a, b0, b1);
                }
            }
        }
        __syncthreads();
    }

    // ---- epilogue: O /= l, write ctx in [b][s][h][d] layout ----
    float inv0 = 1.f / l_sm[w*16+g];
    float inv1 = 1.f / l_sm[w*16+g+8];
    int bb = bh>>4, hh = bh&15;
    int lr0 = l0 + w*16 + g;
    #pragma unroll
    for (int ni=0; ni<8; ni++){
        int d = ni*8 + 2*tig;
        g_ctx[(((size_t)bb*SQ + lr0  )*HN + hh)*DH + d  ] = o[ni][0]*inv0;
        g_ctx[(((size_t)bb*SQ + lr0  )*HN + hh)*DH + d+1] = o[ni][1]*inv0;
        g_ctx[(((size_t)bb*SQ + lr0+8)*HN + hh)*DH + d  ] = o[ni][2]*inv1;
        g_ctx[(((size_t)bb*SQ + lr0+8)*HN + hh)*DH + d+1] = o[ni][3]*inv1;
    }
}

// ---------------------------------------------------------------------------
// K3a: h = ctx @ Wo + bo + hidden  (pre-LayerNorm).  grid (8, 64)
// ---------------------------------------------------------------------------
__global__ __launch_bounds__(256,1) void out_kernel(const float* __restrict__ Wo,
    const float* __restrict__ bo, const float* __restrict__ hidden)
{
    __shared__ float As[128][36];
    __shared__ float Bs[32][132];
    int nb = blockIdx.x*128, rt = blockIdx.y;

    float c[4][4][4];
    #pragma unroll
    for (int i=0;i<4;i++)
        #pragma unroll
        for (int j=0;j<4;j++)
            #pragma unroll
            for (int e=0;e<4;e++) c[i][j][e]=0.f;

    gemm_tile(g_ctx, Wo, rt*128, nb, c, As, Bs);

    int tid=threadIdx.x, w=tid>>5, lane=tid&31, g=lane>>2, tig=lane&3;
    int rows0=(w>>2)*64, cols0=(w&3)*32;
    #pragma unroll
    for (int mi=0; mi<4; mi++){
        #pragma unroll
        for (int ni=0; ni<4; ni++){
            #pragma unroll
            for (int eo=0; eo<4; eo++){
                int row = rows0 + 16*mi + g + ((eo>=2)?8:0);
                int col = cols0 + 8*ni + 2*tig + (eo&1);
                int t = rt*128 + row;
                int e = nb + col;
                float val = c[mi][ni][eo] + bo[e] + hidden[(size_t)t*EM + e];
                g_h[(size_t)t*EM + e] = val;
            }
        }
    }
}

// ---------------------------------------------------------------------------
// K3b: LayerNorm per row.  grid 8192 x 256 threads (4 elems/thread)
// ---------------------------------------------------------------------------
__global__ __launch_bounds__(256,1) void ln_kernel(const float* __restrict__ gamma,
    const float* __restrict__ beta, float* __restrict__ out)
{
    int row = blockIdx.x;
    int tid = threadIdx.x;
    int w = tid>>5, lane = tid&31;
    const float4 x4 = ((const float4*)(g_h + (size_t)row*EM))[tid];
    float s = x4.x + x4.y + x4.z + x4.w;
    float q = x4.x*x4.x + x4.y*x4.y + x4.z*x4.z + x4.w*x4.w;
    #pragma unroll
    for (int off=16; off; off>>=1){
        s += __shfl_xor_sync(0xffffffffu, s, off);
        q += __shfl_xor_sync(0xffffffffu, q, off);
    }
    __shared__ float ss[8], qs[8];
    __shared__ float mean_s, rs_s;
    if (lane==0){ ss[w]=s; qs[w]=q; }
    __syncthreads();
    if (w==0){
        float s2 = (lane<8) ? ss[lane] : 0.f;
        float q2 = (lane<8) ? qs[lane] : 0.f;
        #pragma unroll
        for (int off=4; off; off>>=1){
            s2 += __shfl_xor_sync(0xffffffffu, s2, off);
            q2 += __shfl_xor_sync(0xffffffffu, q2, off);
        }
        if (lane==0){
            float mean = s2 * (1.f/1024.f);
            float var  = fmaxf(q2 * (1.f/1024.f) - mean*mean, 0.f);
            mean_s = mean;
            rs_s   = rsqrtf(var + 1e-12f);
        }
    }
    __syncthreads();
    float mean = mean_s, rs = rs_s;
    float4 gm = ((const float4*)gamma)[tid];
    float4 bt = ((const float4*)beta)[tid];
    float4 y;
    y.x = (x4.x - mean)*rs*gm.x + bt.x;
    y.y = (x4.y - mean)*rs*gm.y + bt.y;
    y.z = (x4.z - mean)*rs*gm.z + bt.z;
    y.w = (x4.w - mean)*rs*gm.w + bt.w;
    ((float4*)(out + (size_t)row*EM))[tid] = y;
}

// ---------------------------------------------------------------------------
extern "C" void kernel_launch(void* const* d_in, const int* in_sizes, int n_in,
                              void* d_out, int out_size)
{
    const float* hidden = (const float*)d_in[0];
    const float* Wq  = (const float*)d_in[1];
    const float* bq  = (const float*)d_in[2];
    const float* Wk  = (const float*)d_in[3];
    const float* bk  = (const float*)d_in[4];
    const float* Wv  = (const float*)d_in[5];
    const float* bv  = (const float*)d_in[6];
    const float* dist= (const float*)d_in[7];
    const float* Wo  = (const float*)d_in[8];
    const float* bo  = (const float*)d_in[9];
    const float* gam = (const float*)d_in[10];
    const float* bet = (const float*)d_in[11];
    float* out = (float*)d_out;

    cudaFuncSetAttribute(attn_kernel, cudaFuncAttributeMaxDynamicSharedMemorySize, ATTN_SMEM);

    qkv_kernel<<<dim3(24,64), 256>>>(hidden, Wq,bq, Wk,bk, Wv,bv);
    attn_kernel<<<dim3(128,8), 256, ATTN_SMEM>>>(dist);
    out_kernel<<<dim3(8,64), 256>>>(Wo, bo, hidden);
    ln_kernel<<<8192, 256>>>(gam, bet, out);
}

// round 3
// speedup vs baseline: 2.1661x; 2.1661x over previous
#include <cuda_runtime.h>
#include <cuda_fp16.h>
#include <cstdint>

#define HN 16
#define DH 64
#define EM 1024
#define SQ 1024
#define BA 8
#define BH (BA*HN)
#define NTOK (BA*SQ)

// Scratch (device globals; allocation-free per harness rules)
__device__ __half g_hid_h[NTOK*EM];
__device__ __half g_wt[3*EM*EM];      // [3072 n][1024 k] (W^T, fp16)
__device__ __half g_wot[EM*EM];       // [1024 n][1024 k]
__device__ __half g_qh[BH*SQ*DH];
__device__ __half g_kh[BH*SQ*DH];
__device__ __half g_vh[BH*SQ*DH];
__device__ __half g_ctx_h[NTOK*EM];
__device__ __half g_dist_h[2047*DH];
__device__ float  g_biasqkv[3*EM];
__device__ float  g_h[NTOK*EM];

// ---------------------------------------------------------------------------
// PTX helpers (all non-'a' features: sm_80-class, compile at sm_103)
// ---------------------------------------------------------------------------
__device__ __forceinline__ uint32_t s2u(const void* p){
    uint32_t a; asm("{ .reg .u64 t; cvta.to.shared.u64 t, %1; cvt.u32.u64 %0, t; }" : "=r"(a) : "l"(p)); return a;
}
__device__ __forceinline__ void ldsm4(uint32_t& r0, uint32_t& r1, uint32_t& r2, uint32_t& r3, uint32_t addr){
    asm volatile("ldmatrix.sync.aligned.m8n8.x4.shared.b16 {%0,%1,%2,%3}, [%4];"
        : "=r"(r0), "=r"(r1), "=r"(r2), "=r"(r3) : "r"(addr));
}
__device__ __forceinline__ void ldsm4t(uint32_t& r0, uint32_t& r1, uint32_t& r2, uint32_t& r3, uint32_t addr){
    asm volatile("ldmatrix.sync.aligned.m8n8.x4.trans.shared.b16 {%0,%1,%2,%3}, [%4];"
        : "=r"(r0), "=r"(r1), "=r"(r2), "=r"(r3) : "r"(addr));
}
__device__ __forceinline__ void mmaf16(float c[4], const uint32_t a[4], uint32_t b0, uint32_t b1){
    asm volatile("mma.sync.aligned.m16n8k16.row.col.f32.f16.f16.f32 "
        "{%0,%1,%2,%3}, {%4,%5,%6,%7}, {%8,%9}, {%0,%1,%2,%3};"
        : "+f"(c[0]), "+f"(c[1]), "+f"(c[2]), "+f"(c[3])
        : "r"(a[0]), "r"(a[1]), "r"(a[2]), "r"(a[3]), "r"(b0), "r"(b1));
}
__device__ __forceinline__ void cp16(uint32_t dst, const void* src){
    asm volatile("cp.async.ca.shared.global [%0], [%1], 16;" :: "r"(dst), "l"(src));
}
__device__ __forceinline__ void cp_commit(){ asm volatile("cp.async.commit_group;" ::: "memory"); }
template<int N> __device__ __forceinline__ void cp_wait(){
    asm volatile("cp.async.wait_group %0;" :: "n"(N) : "memory");
}

// ---------------------------------------------------------------------------
// Pack kernels
// ---------------------------------------------------------------------------
__global__ __launch_bounds__(256) void pack_h_kernel(const float* __restrict__ src,
                                                     __half* __restrict__ dst, int n4)
{
    int i = blockIdx.x*256 + threadIdx.x;
    if (i < n4){
        float4 v = ((const float4*)src)[i];
        __half2* d = (__half2*)dst + i*2;
        d[0] = __floats2half2_rn(v.x, v.y);
        d[1] = __floats2half2_rn(v.z, v.w);
    }
}

// W [k][n] fp32 -> Wt [n][k] fp16 (tiled transpose)
__global__ __launch_bounds__(256) void pack_wt_kernel(const float* __restrict__ W,
                                                      __half* __restrict__ Wt)
{
    __shared__ float t[32][33];
    int bn = blockIdx.x*32, bk = blockIdx.y*32;
    int tx = threadIdx.x & 31, ty = threadIdx.x >> 5;
    #pragma unroll
    for (int i=0;i<32;i+=8)
        t[ty+i][tx] = W[(size_t)(bk+ty+i)*EM + bn+tx];
    __syncthreads();
    #pragma unroll
    for (int i=0;i<32;i+=8)
        Wt[(size_t)(bn+ty+i)*EM + bk+tx] = __float2half_rn(t[tx][ty+i]);
}

__global__ void pack_bias_kernel(const float* bq, const float* bk, const float* bv){
    int b = blockIdx.x;
    const float* s = (b==0) ? bq : (b==1 ? bk : bv);
    g_biasqkv[b*EM + threadIdx.x] = s[threadIdx.x];
}

// ---------------------------------------------------------------------------
// fp16 GEMM: C[128 x 128] tile, K=1024, 4-stage cp.async, ldmatrix + mma16816.
// A [M][1024] half row-major; Bt [N][1024] half (n-major, k contiguous).
// mode 0: qkv epilogue (bias + head-split to g_qh/g_kh/g_vh, fp16)
// mode 1: out epilogue (bias + residual -> g_h fp32)
// ---------------------------------------------------------------------------
#define GLDA 40                 // halves per row (32 data + 8 pad) = 80B
#define GSTG (128*GLDA*2)       // 10240 B per A or B tile
#define GSMEM (4*2*GSTG)        // 81920

__global__ __launch_bounds__(256,2) void gemm_h(const __half* __restrict__ A,
    const __half* __restrict__ Bt, const float* __restrict__ bias,
    const float* __restrict__ resid, int mode)
{
    extern __shared__ char sm[];
    uint32_t sb = s2u(sm);
    int tid = threadIdx.x, w = tid>>5, lane = tid&31;
    int g = lane>>2, tig = lane&3;
    int rows0 = (w>>2)*64, cols0 = (w&3)*32;
    int m0 = blockIdx.x*128, n0 = blockIdx.y*128;

    float c[4][4][4];
    #pragma unroll
    for (int i=0;i<4;i++)
        #pragma unroll
        for (int j=0;j<4;j++){ c[i][j][0]=0.f; c[i][j][1]=0.f; c[i][j][2]=0.f; c[i][j][3]=0.f; }

    auto load_st = [&](int st, int kc){
        uint32_t base = sb + st*2*GSTG;
        const __half* gA = A + (size_t)m0*EM + kc*32;
        const __half* gB = Bt + (size_t)n0*EM + kc*32;
        #pragma unroll
        for (int i=0;i<2;i++){
            int cix = tid + 256*i;
            int row = cix>>2, part = cix&3;
            cp16(base + row*80 + part*16, gA + (size_t)row*EM + part*8);
        }
        #pragma unroll
        for (int i=0;i<2;i++){
            int cix = tid + 256*i;
            int row = cix>>2, part = cix&3;
            cp16(base + GSTG + row*80 + part*16, gB + (size_t)row*EM + part*8);
        }
    };

    #pragma unroll
    for (int s=0;s<3;s++){ load_st(s, s); cp_commit(); }

    int a_r = lane & 15;
    int a_k = (lane>>4)<<3;
    int b_n = (lane&7) + ((lane>=16)?8:0);
    int b_k = (lane&8)?8:0;

    for (int kc=0; kc<32; kc++){
        if (kc+3 < 32) load_st((kc+3)&3, kc+3);
        cp_commit();
        cp_wait<3>();
        __syncthreads();
        uint32_t Ab = sb + (kc&3)*2*GSTG;
        uint32_t Bb = Ab + GSTG;
        #pragma unroll
        for (int ks=0; ks<2; ks++){
            uint32_t a[4][4];
            #pragma unroll
            for (int mi=0;mi<4;mi++)
                ldsm4(a[mi][0],a[mi][1],a[mi][2],a[mi][3],
                      Ab + (rows0+16*mi+a_r)*80 + (ks*16 + a_k)*2);
            #pragma unroll
            for (int ni2=0;ni2<2;ni2++){
                uint32_t b0,b1,b2,b3;
                ldsm4(b0,b1,b2,b3, Bb + (cols0+16*ni2+b_n)*80 + (ks*16 + b_k)*2);
                #pragma unroll
                for (int mi=0;mi<4;mi++){
                    mmaf16(c[mi][2*ni2],   a[mi], b0, b1);
                    mmaf16(c[mi][2*ni2+1], a[mi], b2, b3);
                }
            }
        }
        __syncthreads();
    }

    // epilogue
    #pragma unroll
    for (int mi=0; mi<4; mi++){
        int rowA = rows0 + 16*mi + g;
        int t1 = m0 + rowA, t2 = t1 + 8;
        #pragma unroll
        for (int ni=0; ni<4; ni++){
            int col = cols0 + 8*ni + 2*tig;
            int nglob = n0 + col;
            float bv0 = bias[nglob], bv1 = bias[nglob+1];
            if (mode == 0){
                int mat = nglob>>10, e = nglob&1023, h = e>>6, d = e&63;
                __half* outp = (mat==0) ? g_qh : (mat==1 ? g_kh : g_vh);
                int bb1 = t1>>10, s1 = t1&1023;
                int bb2 = t2>>10, s2 = t2&1023;
                *(__half2*)&outp[(((size_t)(bb1*HN+h))*SQ + s1)*DH + d] =
                    __floats2half2_rn(c[mi][ni][0]+bv0, c[mi][ni][1]+bv1);
                *(__half2*)&outp[(((size_t)(bb2*HN+h))*SQ + s2)*DH + d] =
                    __floats2half2_rn(c[mi][ni][2]+bv0, c[mi][ni][3]+bv1);
            } else {
                const float* r1 = &resid[(size_t)t1*EM + nglob];
                const float* r2 = &resid[(size_t)t2*EM + nglob];
                float2 v1; v1.x = c[mi][ni][0]+bv0+r1[0]; v1.y = c[mi][ni][1]+bv1+r1[1];
                float2 v2; v2.x = c[mi][ni][2]+bv0+r2[0]; v2.y = c[mi][ni][3]+bv1+r2[1];
                *(float2*)&g_h[(size_t)t1*EM + nglob] = v1;
                *(float2*)&g_h[(size_t)t2*EM + nglob] = v2;
            }
        }
    }
}

// ---------------------------------------------------------------------------
// Attention (fp16 mma + ldmatrix), relative_key_query bias.  grid (128, 8)
// ---------------------------------------------------------------------------
#define LDT 144                 // bytes per 64-half row (128 data + 16 pad)
#define LDP 272                 // bytes per 128-half row (256 data + 16 pad)
#define OQ  0
#define OK  18432
#define OV  36864
#define OD  55296               // 256 rows
#define OP  92160               // probs fp16, 128 x 136h
#define OS  126976              // scores fp32, 128 x 132
#define OM  194560
#define OL  195072
#define OA  195584
#define ATTN_SMEM 196096

__global__ __launch_bounds__(256,1) void attn_h()
{
    extern __shared__ char sm[];
    uint32_t sb = s2u(sm);
    float* Ss   = (float*)(sm + OS);
    float* m_sm = (float*)(sm + OM);
    float* l_sm = (float*)(sm + OL);
    float* a_sm = (float*)(sm + OA);
    __half* Ph  = (__half*)(sm + OP);

    int bh = blockIdx.x;
    int l0 = blockIdx.y*128;
    int tid = threadIdx.x;
    int w = tid>>5, lane = tid&31, g = lane>>2, tig = lane&3;

    int a_r = lane & 15;
    int a_k = (lane>>4)<<3;
    int b_n = (lane&7) + ((lane>=16)?8:0);
    int b_k = (lane&8)?8:0;
    int t_k = (lane&7) + ((lane&8)?8:0);
    int t_n = (lane>=16)?8:0;

    // zero dist row 255 (data part only)
    if (tid < 8) *(uint4*)(sm + OD + 255*LDT + tid*16) = make_uint4(0,0,0,0);
    if (tid < 128){ m_sm[tid] = -1e30f; l_sm[tid] = 0.f; }

    // Q tile via cp.async (group 0)
    {
        const __half* qg = g_qh + ((size_t)bh*SQ + l0)*DH;
        #pragma unroll
        for (int i=0;i<4;i++){
            int cix = tid + 256*i;
            int row = cix>>3, part = cix&7;
            cp16(sb + OQ + row*LDT + part*16, qg + (size_t)row*DH + part*8);
        }
        cp_commit();
    }

    float o[8][4];
    #pragma unroll
    for (int i=0;i<8;i++){ o[i][0]=0.f; o[i][1]=0.f; o[i][2]=0.f; o[i][3]=0.f; }

    int rows0 = (w>>1)*32;
    int cols0 = (w&1)*64;

    for (int rt=0; rt<8; rt++){
        int r0 = rt*128;
        // K group
        {
            const __half* kg = g_kh + ((size_t)bh*SQ + r0)*DH;
            #pragma unroll
            for (int i=0;i<4;i++){
                int cix = tid + 256*i;
                int row = cix>>3, part = cix&7;
                cp16(sb + OK + row*LDT + part*16, kg + (size_t)row*DH + part*8);
            }
            cp_commit();
        }
        // D band group (rows 0..254)
        {
            int base = l0 - r0 + 896;
            const __half* dg = g_dist_h + (size_t)base*DH;
            #pragma unroll
            for (int i=0;i<8;i++){
                int cix = tid + 256*i;
                if (cix < 255*8){
                    int row = cix>>3, part = cix&7;
                    cp16(sb + OD + row*LDT + part*16, dg + (size_t)row*DH + part*8);
                }
            }
            cp_commit();
        }
        // V group
        {
            const __half* vg = g_vh + ((size_t)bh*SQ + r0)*DH;
            #pragma unroll
            for (int i=0;i<4;i++){
                int cix = tid + 256*i;
                int row = cix>>3, part = cix&7;
                cp16(sb + OV + row*LDT + part*16, vg + (size_t)row*DH + part*8);
            }
            cp_commit();
        }

        cp_wait<2>();          // Q (rt0) + K ready
        __syncthreads();

        // cache Q A-fragments (used by score and rel_q)
        uint32_t qa[2][4][4];
        #pragma unroll
        for (int mi=0;mi<2;mi++)
            #pragma unroll
            for (int ks=0;ks<4;ks++)
                ldsm4(qa[mi][ks][0],qa[mi][ks][1],qa[mi][ks][2],qa[mi][ks][3],
                      sb + OQ + (rows0+16*mi+a_r)*LDT + (ks*16 + a_k)*2);

        // ---- S = Q @ K^T ----
        {
            float cs[2][8][4];
            #pragma unroll
            for (int i=0;i<2;i++)
                #pragma unroll
                for (int j=0;j<8;j++){ cs[i][j][0]=0.f; cs[i][j][1]=0.f; cs[i][j][2]=0.f; cs[i][j][3]=0.f; }
            #pragma unroll
            for (int ks=0;ks<4;ks++){
                #pragma unroll
                for (int ni2=0;ni2<4;ni2++){
                    uint32_t b0,b1,b2,b3;
                    ldsm4(b0,b1,b2,b3, sb + OK + (cols0+16*ni2+b_n)*LDT + (ks*16 + b_k)*2);
                    #pragma unroll
                    for (int mi=0;mi<2;mi++){
                        mmaf16(cs[mi][2*ni2],   qa[mi][ks], b0, b1);
                        mmaf16(cs[mi][2*ni2+1], qa[mi][ks], b2, b3);
                    }
                }
            }
            #pragma unroll
            for (int mi=0;mi<2;mi++)
                #pragma unroll
                for (int ni=0;ni<8;ni++){
                    int row = rows0+16*mi+g, col = cols0+8*ni+2*tig;
                    Ss[row*132+col]       = cs[mi][ni][0];
                    Ss[row*132+col+1]     = cs[mi][ni][1];
                    Ss[(row+8)*132+col]   = cs[mi][ni][2];
                    Ss[(row+8)*132+col+1] = cs[mi][ni][3];
                }
        }
        __syncthreads();

        cp_wait<1>();          // D ready
        __syncthreads();

        // ---- rel_q: QD = Q @ D^T, scatter S[i][i+127-t] += ----
        #pragma unroll 1
        for (int ch=0; ch<4; ch++){
            int tb = ch*64 + (w&1)*32;
            #pragma unroll 1
            for (int nf2=0; nf2<2; nf2++){
                int n0t = tb + 16*nf2;
                if (n0t+15 < rows0 || n0t > rows0+158) continue;
                float cr[2][2][4];
                #pragma unroll
                for (int i=0;i<2;i++){ cr[i][0][0]=0.f;cr[i][0][1]=0.f;cr[i][0][2]=0.f;cr[i][0][3]=0.f;
                                       cr[i][1][0]=0.f;cr[i][1][1]=0.f;cr[i][1][2]=0.f;cr[i][1][3]=0.f; }
                #pragma unroll
                for (int ks=0;ks<4;ks++){
                    uint32_t b0,b1,b2,b3;
                    ldsm4(b0,b1,b2,b3, sb + OD + (n0t+b_n)*LDT + (ks*16 + b_k)*2);
                    #pragma unroll
                    for (int mi=0;mi<2;mi++){
                        mmaf16(cr[mi][0], qa[mi][ks], b0, b1);
                        mmaf16(cr[mi][1], qa[mi][ks], b2, b3);
                    }
                }
                #pragma unroll
                for (int mi=0;mi<2;mi++)
                    #pragma unroll
                    for (int nf=0;nf<2;nf++){
                        int i0 = rows0+16*mi+g;
                        int t0 = n0t+8*nf+2*tig;
                        #pragma unroll
                        for (int eo=0;eo<4;eo++){
                            int i = i0 + ((eo>=2)?8:0);
                            int t = t0 + (eo&1);
                            int jj = i + 127 - t;
                            if ((unsigned)jj < 128u) Ss[i*132 + jj] += cr[mi][nf][eo];
                        }
                    }
            }
        }
        __syncthreads();

        // ---- rel_k: KD = K @ D^T, scatter S[t+r-127][r] += ----
        {
            uint32_t ka[2][4][4];
            #pragma unroll
            for (int mi=0;mi<2;mi++)
                #pragma unroll
                for (int ks=0;ks<4;ks++)
                    ldsm4(ka[mi][ks][0],ka[mi][ks][1],ka[mi][ks][2],ka[mi][ks][3],
                          sb + OK + (rows0+16*mi+a_r)*LDT + (ks*16 + a_k)*2);
            #pragma unroll 1
            for (int ch=0; ch<4; ch++){
                int tb = ch*64 + (w&1)*32;
                #pragma unroll 1
                for (int nf2=0; nf2<2; nf2++){
                    int n0t = tb + 16*nf2;
                    if (n0t+15 < 96-rows0 || n0t > 254-rows0) continue;
                    float cr[2][2][4];
                    #pragma unroll
                    for (int i=0;i<2;i++){ cr[i][0][0]=0.f;cr[i][0][1]=0.f;cr[i][0][2]=0.f;cr[i][0][3]=0.f;
                                           cr[i][1][0]=0.f;cr[i][1][1]=0.f;cr[i][1][2]=0.f;cr[i][1][3]=0.f; }
                    #pragma unroll
                    for (int ks=0;ks<4;ks++){
                        uint32_t b0,b1,b2,b3;
                        ldsm4(b0,b1,b2,b3, sb + OD + (n0t+b_n)*LDT + (ks*16 + b_k)*2);
                        #pragma unroll
                        for (int mi=0;mi<2;mi++){
                            mmaf16(cr[mi][0], ka[mi][ks], b0, b1);
                            mmaf16(cr[mi][1], ka[mi][ks], b2, b3);
                        }
                    }
                    #pragma unroll
                    for (int mi=0;mi<2;mi++)
                        #pragma unroll
                        for (int nf=0;nf<2;nf++){
                            int r0c = rows0+16*mi+g;
                            int t0 = n0t+8*nf+2*tig;
                            #pragma unroll
                            for (int eo=0;eo<4;eo++){
                                int r = r0c + ((eo>=2)?8:0);
                                int t = t0 + (eo&1);
                                int i = t + r - 127;
                                if ((unsigned)i < 128u) Ss[i*132 + r] += cr[mi][nf][eo];
                            }
                        }
                }
            }
        }
        __syncthreads();

        cp_wait<0>();          // V ready (visibility via next barrier)

        // ---- online softmax, write P as fp16 ----
        #pragma unroll 1
        for (int rr=0; rr<16; rr++){
            int row = w*16 + rr;
            float* srow = Ss + row*132;
            float v0 = srow[lane     ] * 0.125f;
            float v1 = srow[lane + 32] * 0.125f;
            float v2 = srow[lane + 64] * 0.125f;
            float v3 = srow[lane + 96] * 0.125f;
            float mx = fmaxf(fmaxf(v0,v1), fmaxf(v2,v3));
            #pragma unroll
            for (int off=16; off; off>>=1) mx = fmaxf(mx, __shfl_xor_sync(0xffffffffu, mx, off));
            float mo = m_sm[row];
            float mn = fmaxf(mo, mx);
            float p0 = __expf(v0-mn), p1 = __expf(v1-mn), p2 = __expf(v2-mn), p3 = __expf(v3-mn);
            float sum = p0+p1+p2+p3;
            #pragma unroll
            for (int off=16; off; off>>=1) sum += __shfl_xor_sync(0xffffffffu, sum, off);
            __half* prow = Ph + row*136;
            prow[lane     ] = __float2half_rn(p0);
            prow[lane + 32] = __float2half_rn(p1);
            prow[lane + 64] = __float2half_rn(p2);
            prow[lane + 96] = __float2half_rn(p3);
            if (lane==0){
                float al = __expf(mo - mn);
                a_sm[row] = al;
                l_sm[row] = l_sm[row]*al + sum;
                m_sm[row] = mn;
            }
        }
        __syncthreads();

        // ---- O = diag(alpha) O + P @ V ----
        {
            float al0 = a_sm[w*16+g], al1 = a_sm[w*16+g+8];
            #pragma unroll
            for (int ni=0; ni<8; ni++){ o[ni][0]*=al0; o[ni][1]*=al0; o[ni][2]*=al1; o[ni][3]*=al1; }
            uint32_t pa[8][4];
            #pragma unroll
            for (int ks=0;ks<8;ks++)
                ldsm4(pa[ks][0],pa[ks][1],pa[ks][2],pa[ks][3],
                      sb + OP + (w*16 + a_r)*LDP + (ks*16 + a_k)*2);
            #pragma unroll
            for (int ni2=0;ni2<4;ni2++){
                #pragma unroll
                for (int ks=0;ks<8;ks++){
                    uint32_t v0,v1,v2,v3;
                    ldsm4t(v0,v1,v2,v3, sb + OV + (ks*16 + t_k)*LDT + (16*ni2 + t_n)*2);
                    mmaf16(o[2*ni2],   pa[ks], v0, v1);
                    mmaf16(o[2*ni2+1], pa[ks], v2, v3);
                }
            }
        }
        __syncthreads();
    }

    // ---- epilogue: O /= l -> ctx (fp16, [token][E]) ----
    float inv0 = 1.f / l_sm[w*16+g];
    float inv1 = 1.f / l_sm[w*16+g+8];
    int bb = bh>>4, hh = bh&15;
    int s1 = l0 + w*16 + g;
    __half* base1 = g_ctx_h + ((size_t)(bb*SQ + s1  ))*EM + hh*DH;
    __half* base2 = g_ctx_h + ((size_t)(bb*SQ + s1+8))*EM + hh*DH;
    #pragma unroll
    for (int ni=0; ni<8; ni++){
        int d = ni*8 + 2*tig;
        *(__half2*)&base1[d] = __floats2half2_rn(o[ni][0]*inv0, o[ni][1]*inv0);
        *(__half2*)&base2[d] = __floats2half2_rn(o[ni][2]*inv1, o[ni][3]*inv1);
    }
}

// ---------------------------------------------------------------------------
// LayerNorm per row
// ---------------------------------------------------------------------------
__global__ __launch_bounds__(256,1) void ln_kernel(const float* __restrict__ gamma,
    const float* __restrict__ beta, float* __restrict__ out)
{
    int row = blockIdx.x;
    int tid = threadIdx.x;
    int w = tid>>5, lane = tid&31;
    const float4 x4 = ((const float4*)(g_h + (size_t)row*EM))[tid];
    float s = x4.x + x4.y + x4.z + x4.w;
    float q = x4.x*x4.x + x4.y*x4.y + x4.z*x4.z + x4.w*x4.w;
    #pragma unroll
    for (int off=16; off; off>>=1){
        s += __shfl_xor_sync(0xffffffffu, s, off);
        q += __shfl_xor_sync(0xffffffffu, q, off);
    }
    __shared__ float ss[8], qs[8];
    __shared__ float mean_s, rs_s;
    if (lane==0){ ss[w]=s; qs[w]=q; }
    __syncthreads();
    if (w==0){
        float s2 = (lane<8) ? ss[lane] : 0.f;
        float q2 = (lane<8) ? qs[lane] : 0.f;
        #pragma unroll
        for (int off=4; off; off>>=1){
            s2 += __shfl_xor_sync(0xffffffffu, s2, off);
            q2 += __shfl_xor_sync(0xffffffffu, q2, off);
        }
        if (lane==0){
            float mean = s2 * (1.f/1024.f);
            float var  = fmaxf(q2 * (1.f/1024.f) - mean*mean, 0.f);
            mean_s = mean;
            rs_s   = rsqrtf(var + 1e-12f);
        }
    }
    __syncthreads();
    float mean = mean_s, rs = rs_s;
    float4 gm = ((const float4*)gamma)[tid];
    float4 bt = ((const float4*)beta)[tid];
    float4 y;
    y.x = (x4.x - mean)*rs*gm.x + bt.x;
    y.y = (x4.y - mean)*rs*gm.y + bt.y;
    y.z = (x4.z - mean)*rs*gm.z + bt.z;
    y.w = (x4.w - mean)*rs*gm.w + bt.w;
    ((float4*)(out + (size_t)row*EM))[tid] = y;
}

// ---------------------------------------------------------------------------
extern "C" void kernel_launch(void* const* d_in, const int* in_sizes, int n_in,
                              void* d_out, int out_size)
{
    const float* hidden = (const float*)d_in[0];
    const float* Wq  = (const float*)d_in[1];
    const float* bq  = (const float*)d_in[2];
    const float* Wk  = (const float*)d_in[3];
    const float* bk  = (const float*)d_in[4];
    const float* Wv  = (const float*)d_in[5];
    const float* bv  = (const float*)d_in[6];
    const float* dist= (const float*)d_in[7];
    const float* Wo  = (const float*)d_in[8];
    const float* bo  = (const float*)d_in[9];
    const float* gam = (const float*)d_in[10];
    const float* bet = (const float*)d_in[11];
    float* out = (float*)d_out;

    cudaFuncSetAttribute(attn_h, cudaFuncAttributeMaxDynamicSharedMemorySize, ATTN_SMEM);
    cudaFuncSetAttribute(gemm_h, cudaFuncAttributeMaxDynamicSharedMemorySize, GSMEM);

    __half *hidh, *wt, *wot, *ctxh, *disth;
    float *biasq;
    cudaGetSymbolAddress((void**)&hidh,  g_hid_h);
    cudaGetSymbolAddress((void**)&wt,    g_wt);
    cudaGetSymbolAddress((void**)&wot,   g_wot);
    cudaGetSymbolAddress((void**)&ctxh,  g_ctx_h);
    cudaGetSymbolAddress((void**)&disth, g_dist_h);
    cudaGetSymbolAddress((void**)&biasq, g_biasqkv);

    // packing
    pack_h_kernel<<<NTOK*EM/4/256, 256>>>(hidden, hidh, NTOK*EM/4);
    pack_h_kernel<<<128, 256>>>(dist, disth, 2047*DH/4);
    pack_wt_kernel<<<dim3(32,32), 256>>>(Wq, wt);
    pack_wt_kernel<<<dim3(32,32), 256>>>(Wk, wt + EM*EM);
    pack_wt_kernel<<<dim3(32,32), 256>>>(Wv, wt + 2*EM*EM);
    pack_wt_kernel<<<dim3(32,32), 256>>>(Wo, wot);
    pack_bias_kernel<<<3, 1024>>>(bq, bk, bv);

    // QKV projection (N = 3072)
    gemm_h<<<dim3(64,24), 256, GSMEM>>>(hidh, wt, biasq, nullptr, 0);

    // attention
    attn_h<<<dim3(128,8), 256, ATTN_SMEM>>>();

    // output projection + residual (N = 1024)
    gemm_h<<<dim3(64,8), 256, GSMEM>>>(ctxh, wot, bo, hidden, 1);

    ln_kernel<<<NTOK, 256>>>(gam, bet, out);
}

// round 4
// speedup vs baseline: 2.9713x; 1.3718x over previous
#include <cuda_runtime.h>
#include <cuda_fp16.h>
#include <cstdint>

#define HN 16
#define DH 64
#define EM 1024
#define SQ 1024
#define BA 8
#define BH (BA*HN)
#define NTOK (BA*SQ)

// Scratch (device globals; allocation-free per harness rules)
__device__ __half g_hid_h[NTOK*EM];
__device__ __half g_wt[3*EM*EM];      // [3072 n][1024 k] (W^T, fp16)
__device__ __half g_wot[EM*EM];       // [1024 n][1024 k]
__device__ __half g_qh[BH*SQ*DH];
__device__ __half g_kh[BH*SQ*DH];
__device__ __half g_vh[BH*SQ*DH];
__device__ __half g_ctx_h[NTOK*EM];
__device__ __half g_dist_h[2047*DH];
__device__ float  g_biasqkv[3*EM];
__device__ float  g_h[NTOK*EM];

// ---------------------------------------------------------------------------
// PTX helpers (all non-'a' features: sm_80-class, compile at sm_103)
// ---------------------------------------------------------------------------
__device__ __forceinline__ uint32_t s2u(const void* p){
    uint32_t a; asm("{ .reg .u64 t; cvta.to.shared.u64 t, %1; cvt.u32.u64 %0, t; }" : "=r"(a) : "l"(p)); return a;
}
__device__ __forceinline__ void ldsm4(uint32_t& r0, uint32_t& r1, uint32_t& r2, uint32_t& r3, uint32_t addr){
    asm volatile("ldmatrix.sync.aligned.m8n8.x4.shared.b16 {%0,%1,%2,%3}, [%4];"
        : "=r"(r0), "=r"(r1), "=r"(r2), "=r"(r3) : "r"(addr));
}
__device__ __forceinline__ void ldsm4t(uint32_t& r0, uint32_t& r1, uint32_t& r2, uint32_t& r3, uint32_t addr){
    asm volatile("ldmatrix.sync.aligned.m8n8.x4.trans.shared.b16 {%0,%1,%2,%3}, [%4];"
        : "=r"(r0), "=r"(r1), "=r"(r2), "=r"(r3) : "r"(addr));
}
__device__ __forceinline__ void mmaf16(float c[4], const uint32_t a[4], uint32_t b0, uint32_t b1){
    asm volatile("mma.sync.aligned.m16n8k16.row.col.f32.f16.f16.f32 "
        "{%0,%1,%2,%3}, {%4,%5,%6,%7}, {%8,%9}, {%0,%1,%2,%3};"
        : "+f"(c[0]), "+f"(c[1]), "+f"(c[2]), "+f"(c[3])
        : "r"(a[0]), "r"(a[1]), "r"(a[2]), "r"(a[3]), "r"(b0), "r"(b1));
}
__device__ __forceinline__ void cp16(uint32_t dst, const void* src){
    asm volatile("cp.async.ca.shared.global [%0], [%1], 16;" :: "r"(dst), "l"(src));
}
__device__ __forceinline__ void cp_commit(){ asm volatile("cp.async.commit_group;" ::: "memory"); }
template<int N> __device__ __forceinline__ void cp_wait(){
    asm volatile("cp.async.wait_group %0;" :: "n"(N) : "memory");
}

// ---------------------------------------------------------------------------
// Pack kernels
// ---------------------------------------------------------------------------
__global__ __launch_bounds__(256) void pack_h_kernel(const float* __restrict__ src,
                                                     __half* __restrict__ dst, int n4)
{
    int i = blockIdx.x*256 + threadIdx.x;
    if (i < n4){
        float4 v = ((const float4*)src)[i];
        __half2* d = (__half2*)dst + i*2;
        d[0] = __floats2half2_rn(v.x, v.y);
        d[1] = __floats2half2_rn(v.z, v.w);
    }
}

// W [k][n] fp32 -> Wt [n][k] fp16 (tiled transpose)
__global__ __launch_bounds__(256) void pack_wt_kernel(const float* __restrict__ W,
                                                      __half* __restrict__ Wt)
{
    __shared__ float t[32][33];
    int bn = blockIdx.x*32, bk = blockIdx.y*32;
    int tx = threadIdx.x & 31, ty = threadIdx.x >> 5;
    #pragma unroll
    for (int i=0;i<32;i+=8)
        t[ty+i][tx] = W[(size_t)(bk+ty+i)*EM + bn+tx];
    __syncthreads();
    #pragma unroll
    for (int i=0;i<32;i+=8)
        Wt[(size_t)(bn+ty+i)*EM + bk+tx] = __float2half_rn(t[tx][ty+i]);
}

__global__ void pack_bias_kernel(const float* bq, const float* bk, const float* bv){
    int b = blockIdx.x;
    const float* s = (b==0) ? bq : (b==1 ? bk : bv);
    g_biasqkv[b*EM + threadIdx.x] = s[threadIdx.x];
}

// ---------------------------------------------------------------------------
// fp16 GEMM: C[128 x 128] tile, K=1024, 4-stage cp.async, ldmatrix + mma16816.
// ---------------------------------------------------------------------------
#define GSTG (128*40*2)       // 10240 B per A or B tile
#define GSMEM (4*2*GSTG)      // 81920

__global__ __launch_bounds__(256,2) void gemm_h(const __half* __restrict__ A,
    const __half* __restrict__ Bt, const float* __restrict__ bias,
    const float* __restrict__ resid, int mode)
{
    extern __shared__ char sm[];
    uint32_t sb = s2u(sm);
    int tid = threadIdx.x, w = tid>>5, lane = tid&31;
    int g = lane>>2, tig = lane&3;
    int rows0 = (w>>2)*64, cols0 = (w&3)*32;
    int m0 = blockIdx.x*128, n0 = blockIdx.y*128;

    float c[4][4][4];
    #pragma unroll
    for (int i=0;i<4;i++)
        #pragma unroll
        for (int j=0;j<4;j++){ c[i][j][0]=0.f; c[i][j][1]=0.f; c[i][j][2]=0.f; c[i][j][3]=0.f; }

    auto load_st = [&](int st, int kc){
        uint32_t base = sb + st*2*GSTG;
        const __half* gA = A + (size_t)m0*EM + kc*32;
        const __half* gB = Bt + (size_t)n0*EM + kc*32;
        #pragma unroll
        for (int i=0;i<2;i++){
            int cix = tid + 256*i;
            int row = cix>>2, part = cix&3;
            cp16(base + row*80 + part*16, gA + (size_t)row*EM + part*8);
        }
        #pragma unroll
        for (int i=0;i<2;i++){
            int cix = tid + 256*i;
            int row = cix>>2, part = cix&3;
            cp16(base + GSTG + row*80 + part*16, gB + (size_t)row*EM + part*8);
        }
    };

    #pragma unroll
    for (int s=0;s<3;s++){ load_st(s, s); cp_commit(); }

    int a_r = lane & 15;
    int a_k = (lane>>4)<<3;
    int b_n = (lane&7) + ((lane>=16)?8:0);
    int b_k = (lane&8)?8:0;

    for (int kc=0; kc<32; kc++){
        if (kc+3 < 32) load_st((kc+3)&3, kc+3);
        cp_commit();
        cp_wait<3>();
        __syncthreads();
        uint32_t Ab = sb + (kc&3)*2*GSTG;
        uint32_t Bb = Ab + GSTG;
        #pragma unroll
        for (int ks=0; ks<2; ks++){
            uint32_t a[4][4];
            #pragma unroll
            for (int mi=0;mi<4;mi++)
                ldsm4(a[mi][0],a[mi][1],a[mi][2],a[mi][3],
                      Ab + (rows0+16*mi+a_r)*80 + (ks*16 + a_k)*2);
            #pragma unroll
            for (int ni2=0;ni2<2;ni2++){
                uint32_t b0,b1,b2,b3;
                ldsm4(b0,b1,b2,b3, Bb + (cols0+16*ni2+b_n)*80 + (ks*16 + b_k)*2);
                #pragma unroll
                for (int mi=0;mi<4;mi++){
                    mmaf16(c[mi][2*ni2],   a[mi], b0, b1);
                    mmaf16(c[mi][2*ni2+1], a[mi], b2, b3);
                }
            }
        }
        __syncthreads();
    }

    #pragma unroll
    for (int mi=0; mi<4; mi++){
        int rowA = rows0 + 16*mi + g;
        int t1 = m0 + rowA, t2 = t1 + 8;
        #pragma unroll
        for (int ni=0; ni<4; ni++){
            int col = cols0 + 8*ni + 2*tig;
            int nglob = n0 + col;
            float bv0 = bias[nglob], bv1 = bias[nglob+1];
            if (mode == 0){
                int mat = nglob>>10, e = nglob&1023, h = e>>6, d = e&63;
                __half* outp = (mat==0) ? g_qh : (mat==1 ? g_kh : g_vh);
                int bb1 = t1>>10, s1 = t1&1023;
                int bb2 = t2>>10, s2 = t2&1023;
                *(__half2*)&outp[(((size_t)(bb1*HN+h))*SQ + s1)*DH + d] =
                    __floats2half2_rn(c[mi][ni][0]+bv0, c[mi][ni][1]+bv1);
                *(__half2*)&outp[(((size_t)(bb2*HN+h))*SQ + s2)*DH + d] =
                    __floats2half2_rn(c[mi][ni][2]+bv0, c[mi][ni][3]+bv1);
            } else {
                const float* r1 = &resid[(size_t)t1*EM + nglob];
                const float* r2 = &resid[(size_t)t2*EM + nglob];
                float2 v1; v1.x = c[mi][ni][0]+bv0+r1[0]; v1.y = c[mi][ni][1]+bv1+r1[1];
                float2 v2; v2.x = c[mi][ni][2]+bv0+r2[0]; v2.y = c[mi][ni][3]+bv1+r2[1];
                *(float2*)&g_h[(size_t)t1*EM + nglob] = v1;
                *(float2*)&g_h[(size_t)t2*EM + nglob] = v2;
            }
        }
    }
}

// ---------------------------------------------------------------------------
// Register-resident flash attention with relative_key_query bias. grid (128,8)
// Warp w owns score rows 16w..16w+15 (all 128 cols). S in registers; rel bias
// via fp16 QD/KD smem band buffers gathered during softmax; P regs feed PV mma.
// ---------------------------------------------------------------------------
#define LDT 144                 // bytes per 64-half row (128 data + 16 pad)
#define LDB 528                 // bytes per 264-half band row
#define OQ  0
#define OK  18432
#define OV  36864
#define OD  55296               // 256 rows x 144B
#define OQD 92160               // 128 x 264 half
#define OKD 159744
#define ATTN_SMEM 227328

__global__ __launch_bounds__(256,1) void attn_h()
{
    extern __shared__ char sm[];
    uint32_t sb = s2u(sm);

    int bh = blockIdx.x;
    int l0 = blockIdx.y*128;
    int tid = threadIdx.x;
    int w = tid>>5, lane = tid&31, g = lane>>2, tig = lane&3;

    int a_r = lane & 15;
    int a_k = (lane>>4)<<3;
    int b_n = (lane&7) + ((lane>=16)?8:0);
    int b_k = (lane&8)?8:0;
    int t_k = (lane&7) + ((lane&8)?8:0);
    int t_n = (lane>=16)?8:0;

    // zero dist row 255 (read by rel-band ldsm, result never gathered)
    if (tid < 9) *(uint4*)(sm + OD + 255*LDT + tid*16) = make_uint4(0,0,0,0);

    // prologue: G1 = Q + K0 + D0 ; G2 = V0
    {
        const __half* qg = g_qh + ((size_t)bh*SQ + l0)*DH;
        const __half* kg = g_kh + ((size_t)bh*SQ)*DH;
        #pragma unroll
        for (int i=0;i<4;i++){
            int cix = tid + 256*i;
            int row = cix>>3, part = cix&7;
            cp16(sb + OQ + row*LDT + part*16, qg + (size_t)row*DH + part*8);
            cp16(sb + OK + row*LDT + part*16, kg + (size_t)row*DH + part*8);
        }
        const __half* dg = g_dist_h + (size_t)(l0 + 896)*DH;
        #pragma unroll
        for (int i=0;i<8;i++){
            int cix = tid + 256*i;
            if (cix < 255*8){
                int row = cix>>3, part = cix&7;
                cp16(sb + OD + row*LDT + part*16, dg + (size_t)row*DH + part*8);
            }
        }
        cp_commit();
        const __half* vg = g_vh + ((size_t)bh*SQ)*DH;
        #pragma unroll
        for (int i=0;i<4;i++){
            int cix = tid + 256*i;
            int row = cix>>3, part = cix&7;
            cp16(sb + OV + row*LDT + part*16, vg + (size_t)row*DH + part*8);
        }
        cp_commit();
    }

    float o[8][4];
    #pragma unroll
    for (int i=0;i<8;i++){ o[i][0]=0.f; o[i][1]=0.f; o[i][2]=0.f; o[i][3]=0.f; }
    float mrow0 = -1e30f, mrow1 = -1e30f, lrow0 = 0.f, lrow1 = 0.f;

    uint32_t qa[4][4];
    int i0 = 16*w + g;                 // tile-local row of this thread (and +8)

    for (int rt=0; rt<8; rt++){
        cp_wait<1>();
        __syncthreads();               // Q(first)/K/D ready

        if (rt == 0){
            #pragma unroll
            for (int ks=0;ks<4;ks++)
                ldsm4(qa[ks][0],qa[ks][1],qa[ks][2],qa[ks][3],
                      sb + OQ + (16*w+a_r)*LDT + (ks*16 + a_k)*2);
        }
        uint32_t ka[4][4];
        #pragma unroll
        for (int ks=0;ks<4;ks++)
            ldsm4(ka[ks][0],ka[ks][1],ka[ks][2],ka[ks][3],
                  sb + OK + (16*w+a_r)*LDT + (ks*16 + a_k)*2);

        // ---- rel band products: QD[i][t], KD[r][t] -> fp16 smem ----
        #pragma unroll
        for (int c=0; c<4; c++){
            bool nq = (64*c+63 >= 16*w) && (64*c <= 16*w+142);
            bool nk = (64*c+63 >= 112-16*w) && (64*c <= 254-16*w);
            if (!(nq||nk)) continue;
            float qd[8][4], kd[8][4];
            #pragma unroll
            for (int f=0;f<8;f++){
                qd[f][0]=0.f;qd[f][1]=0.f;qd[f][2]=0.f;qd[f][3]=0.f;
                kd[f][0]=0.f;kd[f][1]=0.f;kd[f][2]=0.f;kd[f][3]=0.f;
            }
            #pragma unroll
            for (int ks=0;ks<4;ks++){
                #pragma unroll
                for (int tt=0;tt<4;tt++){
                    uint32_t b0,b1,b2,b3;
                    ldsm4(b0,b1,b2,b3, sb + OD + (64*c+16*tt+b_n)*LDT + (ks*16 + b_k)*2);
                    if (nq){ mmaf16(qd[2*tt], qa[ks], b0, b1); mmaf16(qd[2*tt+1], qa[ks], b2, b3); }
                    if (nk){ mmaf16(kd[2*tt], ka[ks], b0, b1); mmaf16(kd[2*tt+1], ka[ks], b2, b3); }
                }
            }
            #pragma unroll
            for (int f=0;f<8;f++){
                int t0 = 64*c + 8*f + 2*tig;
                if (nq){
                    *(__half2*)(sm + OQD + (size_t)i0*LDB + t0*2)     = __floats2half2_rn(qd[f][0], qd[f][1]);
                    *(__half2*)(sm + OQD + (size_t)(i0+8)*LDB + t0*2) = __floats2half2_rn(qd[f][2], qd[f][3]);
                }
                if (nk){
                    *(__half2*)(sm + OKD + (size_t)i0*LDB + t0*2)     = __floats2half2_rn(kd[f][0], kd[f][1]);
                    *(__half2*)(sm + OKD + (size_t)(i0+8)*LDB + t0*2) = __floats2half2_rn(kd[f][2], kd[f][3]);
                }
            }
        }

        // ---- S = Q @ K^T (warp tile 16 x 128, S in registers) ----
        float cs[16][4];
        #pragma unroll
        for (int f=0;f<16;f++){ cs[f][0]=0.f; cs[f][1]=0.f; cs[f][2]=0.f; cs[f][3]=0.f; }
        #pragma unroll
        for (int ks=0;ks<4;ks++){
            #pragma unroll
            for (int nt=0;nt<8;nt++){
                uint32_t b0,b1,b2,b3;
                ldsm4(b0,b1,b2,b3, sb + OK + (16*nt+b_n)*LDT + (ks*16 + b_k)*2);
                mmaf16(cs[2*nt],   qa[ks], b0, b1);
                mmaf16(cs[2*nt+1], qa[ks], b2, b3);
            }
        }

        __syncthreads();               // S1: QD/KD visible; K/D consumable
        if (rt < 7){
            int r0n = (rt+1)*128;
            const __half* kg = g_kh + ((size_t)bh*SQ + r0n)*DH;
            #pragma unroll
            for (int i=0;i<4;i++){
                int cix = tid + 256*i;
                int row = cix>>3, part = cix&7;
                cp16(sb + OK + row*LDT + part*16, kg + (size_t)row*DH + part*8);
            }
            const __half* dg = g_dist_h + (size_t)(l0 - r0n + 896)*DH;
            #pragma unroll
            for (int i=0;i<8;i++){
                int cix = tid + 256*i;
                if (cix < 255*8){
                    int row = cix>>3, part = cix&7;
                    cp16(sb + OD + row*LDT + part*16, dg + (size_t)row*DH + part*8);
                }
            }
            cp_commit();
        }

        // ---- softmax in registers: bias gather + scale + online update ----
        {
            const __half* QD = (const __half*)(sm + OQD);
            const __half* KD = (const __half*)(sm + OKD);
            float zm0 = -1e30f, zm1 = -1e30f;
            #pragma unroll
            for (int f=0;f<16;f++){
                int j = 8*f + 2*tig;
                int tA = i0 + 127 - j;
                int tB = tA + 8;
                float b00 = __half2float(QD[(size_t)i0*264 + tA])       + __half2float(KD[(size_t)j*264 + tA]);
                float b01 = __half2float(QD[(size_t)i0*264 + tA-1])     + __half2float(KD[(size_t)(j+1)*264 + tA-1]);
                float b10 = __half2float(QD[(size_t)(i0+8)*264 + tB])   + __half2float(KD[(size_t)j*264 + tB]);
                float b11 = __half2float(QD[(size_t)(i0+8)*264 + tB-1]) + __half2float(KD[(size_t)(j+1)*264 + tB-1]);
                cs[f][0] = (cs[f][0] + b00) * 0.125f;
                cs[f][1] = (cs[f][1] + b01) * 0.125f;
                cs[f][2] = (cs[f][2] + b10) * 0.125f;
                cs[f][3] = (cs[f][3] + b11) * 0.125f;
                zm0 = fmaxf(zm0, fmaxf(cs[f][0], cs[f][1]));
                zm1 = fmaxf(zm1, fmaxf(cs[f][2], cs[f][3]));
            }
            zm0 = fmaxf(zm0, __shfl_xor_sync(0xffffffffu, zm0, 1));
            zm0 = fmaxf(zm0, __shfl_xor_sync(0xffffffffu, zm0, 2));
            zm1 = fmaxf(zm1, __shfl_xor_sync(0xffffffffu, zm1, 1));
            zm1 = fmaxf(zm1, __shfl_xor_sync(0xffffffffu, zm1, 2));
            float mn0 = fmaxf(mrow0, zm0), mn1 = fmaxf(mrow1, zm1);
            float al0 = __expf(mrow0 - mn0), al1 = __expf(mrow1 - mn1);
            float s0 = 0.f, s1 = 0.f;
            uint32_t p[16][2];
            #pragma unroll
            for (int f=0;f<16;f++){
                float p00 = __expf(cs[f][0]-mn0), p01 = __expf(cs[f][1]-mn0);
                float p10 = __expf(cs[f][2]-mn1), p11 = __expf(cs[f][3]-mn1);
                s0 += p00 + p01; s1 += p10 + p11;
                __half2 hA = __floats2half2_rn(p00, p01); p[f][0] = *(uint32_t*)&hA;
                __half2 hB = __floats2half2_rn(p10, p11); p[f][1] = *(uint32_t*)&hB;
            }
            s0 += __shfl_xor_sync(0xffffffffu, s0, 1);
            s0 += __shfl_xor_sync(0xffffffffu, s0, 2);
            s1 += __shfl_xor_sync(0xffffffffu, s1, 1);
            s1 += __shfl_xor_sync(0xffffffffu, s1, 2);
            lrow0 = lrow0*al0 + s0; lrow1 = lrow1*al1 + s1;
            mrow0 = mn0; mrow1 = mn1;
            #pragma unroll
            for (int ni=0;ni<8;ni++){ o[ni][0]*=al0; o[ni][1]*=al0; o[ni][2]*=al1; o[ni][3]*=al1; }

            if (rt == 7) { cp_wait<0>(); } else { cp_wait<1>(); }
            __syncthreads();           // V ready

            // ---- O += P @ V (P fragments from registers) ----
            #pragma unroll
            for (int kk=0;kk<8;kk++){
                uint32_t a[4] = { p[2*kk][0], p[2*kk][1], p[2*kk+1][0], p[2*kk+1][1] };
                #pragma unroll
                for (int ni2=0;ni2<4;ni2++){
                    uint32_t v0,v1,v2,v3;
                    ldsm4t(v0,v1,v2,v3, sb + OV + (16*kk + t_k)*LDT + (16*ni2 + t_n)*2);
                    mmaf16(o[2*ni2],   a, v0, v1);
                    mmaf16(o[2*ni2+1], a, v2, v3);
                }
            }
        }

        __syncthreads();               // S2: V consumable
        if (rt < 7){
            int r0n = (rt+1)*128;
            const __half* vg = g_vh + ((size_t)bh*SQ + r0n)*DH;
            #pragma unroll
            for (int i=0;i<4;i++){
                int cix = tid + 256*i;
                int row = cix>>3, part = cix&7;
                cp16(sb + OV + row*LDT + part*16, vg + (size_t)row*DH + part*8);
            }
            cp_commit();
        }
    }

    // ---- epilogue: O /= l -> ctx (fp16, [token][E]) ----
    float inv0 = 1.f / lrow0;
    float inv1 = 1.f / lrow1;
    int bb = bh>>4, hh = bh&15;
    int s1r = l0 + 16*w + g;
    __half* base1 = g_ctx_h + ((size_t)(bb*SQ + s1r  ))*EM + hh*DH;
    __half* base2 = g_ctx_h + ((size_t)(bb*SQ + s1r+8))*EM + hh*DH;
    #pragma unroll
    for (int ni=0; ni<8; ni++){
        int d = ni*8 + 2*tig;
        *(__half2*)&base1[d] = __floats2half2_rn(o[ni][0]*inv0, o[ni][1]*inv0);
        *(__half2*)&base2[d] = __floats2half2_rn(o[ni][2]*inv1, o[ni][3]*inv1);
    }
}

// ---------------------------------------------------------------------------
// LayerNorm per row
// ---------------------------------------------------------------------------
__global__ __launch_bounds__(256,1) void ln_kernel(const float* __restrict__ gamma,
    const float* __restrict__ beta, float* __restrict__ out)
{
    int row = blockIdx.x;
    int tid = threadIdx.x;
    int w = tid>>5, lane = tid&31;
    const float4 x4 = ((const float4*)(g_h + (size_t)row*EM))[tid];
    float s = x4.x + x4.y + x4.z + x4.w;
    float q = x4.x*x4.x + x4.y*x4.y + x4.z*x4.z + x4.w*x4.w;
    #pragma unroll
    for (int off=16; off; off>>=1){
        s += __shfl_xor_sync(0xffffffffu, s, off);
        q += __shfl_xor_sync(0xffffffffu, q, off);
    }
    __shared__ float ss[8], qs[8];
    __shared__ float mean_s, rs_s;
    if (lane==0){ ss[w]=s; qs[w]=q; }
    __syncthreads();
    if (w==0){
        float s2 = (lane<8) ? ss[lane] : 0.f;
        float q2 = (lane<8) ? qs[lane] : 0.f;
        #pragma unroll
        for (int off=4; off; off>>=1){
            s2 += __shfl_xor_sync(0xffffffffu, s2, off);
            q2 += __shfl_xor_sync(0xffffffffu, q2, off);
        }
        if (lane==0){
            float mean = s2 * (1.f/1024.f);
            float var  = fmaxf(q2 * (1.f/1024.f) - mean*mean, 0.f);
            mean_s = mean;
            rs_s   = rsqrtf(var + 1e-12f);
        }
    }
    __syncthreads();
    float mean = mean_s, rs = rs_s;
    float4 gm = ((const float4*)gamma)[tid];
    float4 bt = ((const float4*)beta)[tid];
    float4 y;
    y.x = (x4.x - mean)*rs*gm.x + bt.x;
    y.y = (x4.y - mean)*rs*gm.y + bt.y;
    y.z = (x4.z - mean)*rs*gm.z + bt.z;
    y.w = (x4.w - mean)*rs*gm.w + bt.w;
    ((float4*)(out + (size_t)row*EM))[tid] = y;
}

// ---------------------------------------------------------------------------
extern "C" void kernel_launch(void* const* d_in, const int* in_sizes, int n_in,
                              void* d_out, int out_size)
{
    const float* hidden = (const float*)d_in[0];
    const float* Wq  = (const float*)d_in[1];
    const float* bq  = (const float*)d_in[2];
    const float* Wk  = (const float*)d_in[3];
    const float* bk  = (const float*)d_in[4];
    const float* Wv  = (const float*)d_in[5];
    const float* bv  = (const float*)d_in[6];
    const float* dist= (const float*)d_in[7];
    const float* Wo  = (const float*)d_in[8];
    const float* bo  = (const float*)d_in[9];
    const float* gam = (const float*)d_in[10];
    const float* bet = (const float*)d_in[11];
    float* out = (float*)d_out;

    cudaFuncSetAttribute(attn_h, cudaFuncAttributeMaxDynamicSharedMemorySize, ATTN_SMEM);
    cudaFuncSetAttribute(gemm_h, cudaFuncAttributeMaxDynamicSharedMemorySize, GSMEM);

    __half *hidh, *wt, *wot, *ctxh, *disth;
    float *biasq;
    cudaGetSymbolAddress((void**)&hidh,  g_hid_h);
    cudaGetSymbolAddress((void**)&wt,    g_wt);
    cudaGetSymbolAddress((void**)&wot,   g_wot);
    cudaGetSymbolAddress((void**)&ctxh,  g_ctx_h);
    cudaGetSymbolAddress((void**)&disth, g_dist_h);
    cudaGetSymbolAddress((void**)&biasq, g_biasqkv);

    // packing
    pack_h_kernel<<<NTOK*EM/4/256, 256>>>(hidden, hidh, NTOK*EM/4);
    pack_h_kernel<<<128, 256>>>(dist, disth, 2047*DH/4);
    pack_wt_kernel<<<dim3(32,32), 256>>>(Wq, wt);
    pack_wt_kernel<<<dim3(32,32), 256>>>(Wk, wt + EM*EM);
    pack_wt_kernel<<<dim3(32,32), 256>>>(Wv, wt + 2*EM*EM);
    pack_wt_kernel<<<dim3(32,32), 256>>>(Wo, wot);
    pack_bias_kernel<<<3, 1024>>>(bq, bk, bv);

    // QKV projection (N = 3072)
    gemm_h<<<dim3(64,24), 256, GSMEM>>>(hidh, wt, biasq, nullptr, 0);

    // attention
    attn_h<<<dim3(128,8), 256, ATTN_SMEM>>>();

    // output projection + residual (N = 1024)
    gemm_h<<<dim3(64,8), 256, GSMEM>>>(ctxh, wot, bo, hidden, 1);

    ln_kernel<<<NTOK, 256>>>(gam, bet, out);
}